// round 8
// baseline (speedup 1.0000x reference)
#include <cuda_runtime.h>
#include <cuda_fp16.h>
#include <math.h>
#include <stdint.h>

// Problem shape (fixed by dataset): n=8192, d=256, n_cls=128
#define NMAX 8192
#define DVAL 256

#define ALPHA 10.0f
#define BETA  2.0f
#define BASE  0.7f

// ---- scratch (static __device__ arrays; no allocations allowed) ----
__device__ __half    g_simh[(size_t)NMAX * (size_t)NMAX];  // 128 MB fp16 sims
__device__ __half    g_xh[(size_t)NMAX * DVAL];            // fp16 X (4 MB)
__device__ float     g_lastsim[NMAX];                      // exact fp32 sims of last row
__device__ unsigned  g_minpos_enc[NMAX];
__device__ unsigned  g_maxneg_enc[NMAX];
__device__ float     g_rowloss[NMAX];
__device__ int       g_validf[NMAX];
__device__ float     g_last[4];

// ---- ordered-uint encoding so atomicMin/atomicMax work on floats ----
__device__ __forceinline__ unsigned fenc(float f) {
    unsigned u = __float_as_uint(f);
    return (u & 0x80000000u) ? ~u : (u | 0x80000000u);
}
__device__ __forceinline__ float fdec(unsigned u) {
    return (u & 0x80000000u) ? __uint_as_float(u & 0x7fffffffu)
                             : __uint_as_float(~u);
}
__device__ __forceinline__ float softplus_f(float x) {
    if (x > 15.f) return x;
    return log1pf(__expf(x));
}
__device__ __forceinline__ uint32_t s2u(const void* p) {
    uint32_t a;
    asm("{ .reg .u64 t; cvta.to.shared.u64 t, %1; cvt.u32.u64 %0, t; }"
        : "=r"(a) : "l"(p));
    return a;
}

// ============================================================================
// Pass -1: convert X to fp16 once
// ============================================================================
__global__ __launch_bounds__(256)
void cvt_kernel(const float* __restrict__ X, int total4)
{
    int i = blockIdx.x * blockDim.x + threadIdx.x;
    if (i >= total4) return;
    float4 v = ((const float4*)X)[i];
    __half2* o = (__half2*)g_xh;
    o[i * 2]     = __floats2half2_rn(v.x, v.y);
    o[i * 2 + 1] = __floats2half2_rn(v.z, v.w);
}

// ============================================================================
// Pass 0: init per-row min/max encodings
// ============================================================================
__global__ void init_kernel(int n) {
    int i = blockIdx.x * blockDim.x + threadIdx.x;
    if (i < n) {
        g_minpos_enc[i] = 0xFF800000u;  // fenc(+inf)
        g_maxneg_enc[i] = 0x007FFFFFu;  // fenc(-inf)
    }
}

// ============================================================================
// Pass A: fp16 mma.sync (m16n8k16) GEMM. CTA 256x128 (8 warps, warp tile
// 64x64), BK=64 double-buffered cp.async, SW128-swizzled smem, ldmatrix.x4.
// Epilogue: fused row min-pos/max-neg + fp16 store.
// ============================================================================
#define BK     64
#define NCHUNK (DVAL / BK)       // 4
#define ATILEB 32768             // 256 rows * 128 B
#define BTILEB 16384             // 128 rows * 128 B
#define BUFB   (ATILEB + BTILEB) // 49152
#define SMEM_BYTES (2 * BUFB)    // 98304

__device__ __forceinline__ void mma_f16(float* c, const uint32_t* a, const uint32_t* b)
{
    asm volatile(
        "mma.sync.aligned.m16n8k16.row.col.f32.f16.f16.f32 "
        "{%0,%1,%2,%3}, {%4,%5,%6,%7}, {%8,%9}, {%0,%1,%2,%3};"
        : "+f"(c[0]), "+f"(c[1]), "+f"(c[2]), "+f"(c[3])
        : "r"(a[0]), "r"(a[1]), "r"(a[2]), "r"(a[3]), "r"(b[0]), "r"(b[1]));
}

__global__ __launch_bounds__(256, 1)
void gemm_tc_kernel(const int* __restrict__ tgt, int n)
{
    extern __shared__ char smc[];
    const uint32_t smb = s2u(smc);
    const int tid   = threadIdx.x;
    const int wid   = tid >> 5;
    const int lane  = tid & 31;
    const int g     = lane >> 2;
    const int t4    = lane & 3;
    const int warpM = wid >> 1;            // 0..3 (64 rows each)
    const int warpN = wid & 1;             // 0..1 (64 cols each)
    const int rowBase = blockIdx.y * 256;
    const int colBase = blockIdx.x * 128;

    // ldmatrix per-lane address components
    const int lm_m   = lane >> 3;                        // matrix index 0..3
    const int lm_r   = (lane & 7) + ((lm_m & 1) << 3);   // row 0..15
    const int lm_cs  = (lm_m >> 1) << 4;                 // 0 or 16 bytes
    const int lm_swz = (lane & 7) << 4;                  // swizzle XOR

    // ---- async chunk loader: A 2048 x 16B + B 1024 x 16B ----
    auto load_chunk = [&](int c, int buf) {
        const uint32_t base = smb + buf * BUFB;
#pragma unroll
        for (int it = 0; it < 12; ++it) {
            int idx = tid + it * 256;       // 0..3071
            int isB = (idx >= 2048);
            int li  = isB ? idx - 2048 : idx;
            int r   = li >> 3;
            int f   = li & 7;
            int grow = (isB ? colBase : rowBase) + r;
            uint32_t dst = base + isB * ATILEB + r * 128 + ((f * 16) ^ ((r & 7) << 4));
            const __half* src = &g_xh[(size_t)grow * DVAL + c * BK + f * 8];
            asm volatile("cp.async.cg.shared.global [%0], [%1], 16;"
                         :: "r"(dst), "l"(src) : "memory");
        }
        asm volatile("cp.async.commit_group;" ::: "memory");
    };

    float acc[4][8][4];
#pragma unroll
    for (int i = 0; i < 4; i++)
#pragma unroll
        for (int j = 0; j < 8; j++)
#pragma unroll
            for (int q = 0; q < 4; q++) acc[i][j][q] = 0.f;

    load_chunk(0, 0);

    for (int c = 0; c < NCHUNK; ++c) {
        const int buf = c & 1;
        if (c + 1 < NCHUNK) {
            load_chunk(c + 1, buf ^ 1);
            asm volatile("cp.async.wait_group 1;" ::: "memory");
        } else {
            asm volatile("cp.async.wait_group 0;" ::: "memory");
        }
        __syncthreads();

        const uint32_t Abase = smb + buf * BUFB;
        const uint32_t Bbase = Abase + ATILEB;

#pragma unroll
        for (int q = 0; q < 4; ++q) {       // 4 k-steps of 16
            const int kb = q * 32;          // bytes
            const uint32_t cswz = (uint32_t)((kb + lm_cs) ^ lm_swz);
            uint32_t af[4][4], bf[8][2];
#pragma unroll
            for (int i = 0; i < 4; ++i) {
                uint32_t addr = Abase + (uint32_t)((warpM * 64 + i * 16 + lm_r) * 128) + cswz;
                asm volatile("ldmatrix.sync.aligned.m8n8.x4.shared.b16 {%0,%1,%2,%3}, [%4];"
                             : "=r"(af[i][0]), "=r"(af[i][1]), "=r"(af[i][2]), "=r"(af[i][3])
                             : "r"(addr));
            }
#pragma unroll
            for (int jj = 0; jj < 4; ++jj) {
                uint32_t r0, r1, r2, r3;
                uint32_t addr = Bbase + (uint32_t)((warpN * 64 + jj * 16 + lm_r) * 128) + cswz;
                asm volatile("ldmatrix.sync.aligned.m8n8.x4.shared.b16 {%0,%1,%2,%3}, [%4];"
                             : "=r"(r0), "=r"(r1), "=r"(r2), "=r"(r3)
                             : "r"(addr));
                bf[jj * 2][0]     = r0; bf[jj * 2][1]     = r2;
                bf[jj * 2 + 1][0] = r1; bf[jj * 2 + 1][1] = r3;
            }
#pragma unroll
            for (int i = 0; i < 4; ++i)
#pragma unroll
                for (int j = 0; j < 8; ++j)
                    mma_f16(acc[i][j], af[i], bf[j]);
        }
        __syncthreads();
    }

    // ---- epilogue: fp16 sim store + fused per-row min-pos / max-neg ----
#pragma unroll
    for (int i = 0; i < 4; ++i) {
        const int r0 = rowBase + warpM * 64 + i * 16 + g;
        const int r1 = r0 + 8;
        const int tr0 = tgt[r0], tr1 = tgt[r1];
        float mp0 = __int_as_float(0x7f800000), mn0 = __int_as_float(0xff800000);
        float mp1 = mp0, mn1 = mn0;
#pragma unroll
        for (int j = 0; j < 8; ++j) {
            const int col = colBase + warpN * 64 + j * 8 + t4 * 2;
            const int tc0 = tgt[col], tc1 = tgt[col + 1];
            float v00 = acc[i][j][0], v01 = acc[i][j][1];
            float v10 = acc[i][j][2], v11 = acc[i][j][3];
            if (tc0 == tr0) { if (col     != r0) mp0 = fminf(mp0, v00); }
            else            mn0 = fmaxf(mn0, v00);
            if (tc1 == tr0) { if (col + 1 != r0) mp0 = fminf(mp0, v01); }
            else            mn0 = fmaxf(mn0, v01);
            if (tc0 == tr1) { if (col     != r1) mp1 = fminf(mp1, v10); }
            else            mn1 = fmaxf(mn1, v10);
            if (tc1 == tr1) { if (col + 1 != r1) mp1 = fminf(mp1, v11); }
            else            mn1 = fmaxf(mn1, v11);

            *(half2*)&g_simh[(size_t)r0 * n + col] = __floats2half2_rn(v00, v01);
            *(half2*)&g_simh[(size_t)r1 * n + col] = __floats2half2_rn(v10, v11);
        }
#pragma unroll
        for (int o = 1; o < 4; o <<= 1) {
            mp0 = fminf(mp0, __shfl_xor_sync(0xffffffffu, mp0, o));
            mn0 = fmaxf(mn0, __shfl_xor_sync(0xffffffffu, mn0, o));
            mp1 = fminf(mp1, __shfl_xor_sync(0xffffffffu, mp1, o));
            mn1 = fmaxf(mn1, __shfl_xor_sync(0xffffffffu, mn1, o));
        }
        if (t4 == 0) {
            atomicMin(&g_minpos_enc[r0], fenc(mp0));
            atomicMax(&g_maxneg_enc[r0], fenc(mn0));
            atomicMin(&g_minpos_enc[r1], fenc(mp1));
            atomicMax(&g_maxneg_enc[r1], fenc(mn1));
        }
    }
}

// ============================================================================
// Pass A': exact fp32 sims of the LAST row. 8-way d-split per column.
// ============================================================================
__global__ __launch_bounds__(256)
void lastrow_kernel(const float* __restrict__ X, int n)
{
    __shared__ float xl[DVAL];
    const int t = threadIdx.x;
    xl[t] = X[(size_t)(n - 1) * DVAL + t];
    __syncthreads();
    const int gt  = blockIdx.x * 256 + t;
    const int col = gt >> 3;
    const int seg = gt & 7;
    const float4* xr  = (const float4*)&X[(size_t)col * DVAL + seg * 32];
    const float4* xl4 = (const float4*)&xl[seg * 32];
    float s = 0.f;
#pragma unroll
    for (int k = 0; k < 8; ++k) {
        float4 a = xr[k], b = xl4[k];
        s += a.x * b.x + a.y * b.y + a.z * b.z + a.w * b.w;
    }
#pragma unroll
    for (int o = 4; o; o >>= 1) s += __shfl_xor_sync(0xffffffffu, s, o);
    if (seg == 0) g_lastsim[col] = s;
}

// ============================================================================
// Pass B: warp-per-row (8 rows per CTA). Targets staged once per CTA.
// ============================================================================
__global__ __launch_bounds__(256)
void row_pass_kernel(const int* __restrict__ tgt,
                     const float* __restrict__ marginp, int n)
{
    extern __shared__ int sh_t[];          // n ints (32 KB)
    const int tid  = threadIdx.x;
    const int w    = tid >> 5;
    const int lane = tid & 31;
    for (int i = tid; i < n; i += 256) sh_t[i] = tgt[i];
    __syncthreads();

    const int row = blockIdx.x * 8 + w;
    const float margin = *marginp;
    const int tr = sh_t[row];
    const float minpos = fdec(g_minpos_enc[row]);
    const float maxneg = fdec(g_maxneg_enc[row]);
    const bool isLast = (row == n - 1);

    float psum = 0.f, nsum = 0.f, pcnt = 0.f, ncnt = 0.f;
    float lps = 0.f, lns = 0.f, lpc = 0.f, lnc = 0.f;

    if (!isLast) {
        const float4* srow4 = (const float4*)(g_simh + (size_t)row * n);
        for (int i = lane; i < n / 8; i += 32) {
            float4 raw = srow4[i];
            const __half2* h2 = (const __half2*)&raw;
            float sv[8];
#pragma unroll
            for (int p = 0; p < 4; ++p) {
                float2 f2 = __half22float2(h2[p]);
                sv[p * 2] = f2.x; sv[p * 2 + 1] = f2.y;
            }
#pragma unroll
            for (int j = 0; j < 8; ++j) {
                int col = i * 8 + j;
                float s = sv[j];
                if (sh_t[col] != tr) {
                    if (s + margin - minpos > 0.f) {
                        nsum += softplus_f(ALPHA * (s - BASE));
                        ncnt += 1.f;
                    }
                } else if (col != row) {
                    if (maxneg - s + margin > 0.f) {
                        psum += softplus_f(-BETA * (s - BASE));
                        pcnt += 1.f;
                    }
                }
            }
        }
    } else {
        const float4* srow4 = (const float4*)g_lastsim;
        for (int i = lane; i < n / 4; i += 32) {
            float4 v = srow4[i];
            float sv[4] = {v.x, v.y, v.z, v.w};
#pragma unroll
            for (int j = 0; j < 4; ++j) {
                int col = i * 4 + j;
                float s = sv[j];
                if (sh_t[col] != tr) {
                    lns += s; lnc += 1.f;
                    if (s + margin - minpos > 0.f) {
                        nsum += softplus_f(ALPHA * (s - BASE));
                        ncnt += 1.f;
                    }
                } else if (col != row) {
                    lps += s; lpc += 1.f;
                    if (maxneg - s + margin > 0.f) {
                        psum += softplus_f(-BETA * (s - BASE));
                        pcnt += 1.f;
                    }
                }
            }
        }
    }

#pragma unroll
    for (int o = 16; o; o >>= 1) {
        psum += __shfl_xor_sync(0xffffffffu, psum, o);
        pcnt += __shfl_xor_sync(0xffffffffu, pcnt, o);
        nsum += __shfl_xor_sync(0xffffffffu, nsum, o);
        ncnt += __shfl_xor_sync(0xffffffffu, ncnt, o);
    }
    if (lane == 0) {
        float pm = psum / fmaxf(pcnt, 1.f);
        float nm = nsum / fmaxf(ncnt, 1.f);
        g_rowloss[row] = (2.f / BETA) * pm + (2.f / ALPHA) * nm;
        g_validf[row]  = (pcnt >= 1.f && ncnt >= 1.f) ? 1 : 0;
    }
    if (isLast) {
#pragma unroll
        for (int o = 16; o; o >>= 1) {
            lps += __shfl_xor_sync(0xffffffffu, lps, o);
            lpc += __shfl_xor_sync(0xffffffffu, lpc, o);
            lns += __shfl_xor_sync(0xffffffffu, lns, o);
            lnc += __shfl_xor_sync(0xffffffffu, lnc, o);
        }
        if (lane == 0) {
            g_last[0] = lps; g_last[1] = lpc;
            g_last[2] = lns; g_last[3] = lnc;
        }
    }
}

// ============================================================================
// Pass C: final deterministic reduction -> out[4]
// ============================================================================
__global__ __launch_bounds__(1024)
void final_kernel(float* __restrict__ out, int n)
{
    const int t = threadIdx.x;
    float ls = 0.f, inv = 0.f;
    for (int i = t; i < n; i += 1024) {
        if (g_validf[i]) ls += g_rowloss[i];
        else             inv += 1.f;
    }
    __shared__ float red[1024];
    __shared__ float red2[1024];
    red[t] = ls; red2[t] = inv; __syncthreads();
    for (int s = 512; s; s >>= 1) {
        if (t < s) { red[t] += red[t + s]; red2[t] += red2[t + s]; }
        __syncthreads();
    }
    if (t == 0) {
        out[0] = red[0] / (float)n;
        out[1] = red2[0] / (float)n;
        out[2] = g_last[0] / fmaxf(g_last[1], 1.f);
        out[3] = g_last[2] / fmaxf(g_last[3], 1.f);
    }
}

// ============================================================================
extern "C" void kernel_launch(void* const* d_in, const int* in_sizes, int n_in,
                              void* d_out, int out_size)
{
    const float* x      = (const float*)d_in[0];
    const int*   tgt    = (const int*)d_in[1];
    const float* margin = (const float*)d_in[2];
    int n = in_sizes[1];

    cudaFuncSetAttribute(gemm_tc_kernel,
                         cudaFuncAttributeMaxDynamicSharedMemorySize, SMEM_BYTES);

    cvt_kernel<<<(n * DVAL / 4 + 255) / 256, 256>>>(x, n * DVAL / 4);
    init_kernel<<<(n + 255) / 256, 256>>>(n);
    dim3 grid(n / 128, n / 256);
    gemm_tc_kernel<<<grid, 256, SMEM_BYTES>>>(tgt, n);
    lastrow_kernel<<<n * 8 / 256, 256>>>(x, n);
    row_pass_kernel<<<n / 8, 256, NMAX * 4>>>(tgt, margin, n);
    final_kernel<<<1, 1024>>>((float*)d_out, n);
}

// round 9
// speedup vs baseline: 1.2653x; 1.2653x over previous
#include <cuda_runtime.h>
#include <cuda_fp16.h>
#include <math.h>
#include <stdint.h>

// Problem shape (fixed by dataset): n=8192, d=256, n_cls=128
#define NMAX 8192
#define DVAL 256

#define ALPHA 10.0f
#define BETA  2.0f
#define BASE  0.7f

// ---- scratch (static __device__ arrays; no allocations allowed) ----
__device__ __half    g_simh[(size_t)NMAX * (size_t)NMAX];  // 128 MB fp16 sims
__device__ __half    g_xh[(size_t)NMAX * DVAL];            // fp16 X (4 MB)
__device__ float     g_lastsim[NMAX];                      // exact fp32 sims of last row
__device__ unsigned  g_minpos_enc[NMAX];
__device__ unsigned  g_maxneg_enc[NMAX];
__device__ float     g_rowloss[NMAX];
__device__ int       g_validf[NMAX];
__device__ float     g_last[4];

// ---- ordered-uint encoding so atomicMin/atomicMax work on floats ----
__device__ __forceinline__ unsigned fenc(float f) {
    unsigned u = __float_as_uint(f);
    return (u & 0x80000000u) ? ~u : (u | 0x80000000u);
}
__device__ __forceinline__ float fdec(unsigned u) {
    return (u & 0x80000000u) ? __uint_as_float(u & 0x7fffffffu)
                             : __uint_as_float(~u);
}
// Fast softplus: args here are in [-12, 3]; pos-term (dominant) args ~+1.4
// where __expf/__logf are ~1e-6 accurate. No overflow possible.
__device__ __forceinline__ float softplus_f(float x) {
    return __logf(1.f + __expf(x));
}
__device__ __forceinline__ uint32_t s2u(const void* p) {
    uint32_t a;
    asm("{ .reg .u64 t; cvta.to.shared.u64 t, %1; cvt.u32.u64 %0, t; }"
        : "=r"(a) : "l"(p));
    return a;
}

// ============================================================================
// Pass -1: convert X to fp16 once
// ============================================================================
__global__ __launch_bounds__(256)
void cvt_kernel(const float* __restrict__ X, int total4)
{
    int i = blockIdx.x * blockDim.x + threadIdx.x;
    if (i >= total4) return;
    float4 v = ((const float4*)X)[i];
    __half2* o = (__half2*)g_xh;
    o[i * 2]     = __floats2half2_rn(v.x, v.y);
    o[i * 2 + 1] = __floats2half2_rn(v.z, v.w);
}

// ============================================================================
// Pass 0: init per-row min/max encodings
// ============================================================================
__global__ void init_kernel(int n) {
    int i = blockIdx.x * blockDim.x + threadIdx.x;
    if (i < n) {
        g_minpos_enc[i] = 0xFF800000u;  // fenc(+inf)
        g_maxneg_enc[i] = 0x007FFFFFu;  // fenc(-inf)
    }
}

// ============================================================================
// Pass A: fp16 mma.sync (m16n8k16) GEMM. CTA 128x128, 8 warps (2x4),
// warp tile 64x32, BK=64 double-buffered cp.async, SW128-swizzled smem,
// ldmatrix.x4 fragment loads. Epilogue: fused row min-pos/max-neg + fp16 store.
// ============================================================================
#define BK     64
#define NCHUNK (DVAL / BK)       // 4
#define TILEB  16384             // 128 rows * 128 B
#define BUFB   (2 * TILEB)
#define SMEM_BYTES (2 * BUFB)    // 65536

__device__ __forceinline__ void mma_f16(float* c, const uint32_t* a, const uint32_t* b)
{
    asm volatile(
        "mma.sync.aligned.m16n8k16.row.col.f32.f16.f16.f32 "
        "{%0,%1,%2,%3}, {%4,%5,%6,%7}, {%8,%9}, {%0,%1,%2,%3};"
        : "+f"(c[0]), "+f"(c[1]), "+f"(c[2]), "+f"(c[3])
        : "r"(a[0]), "r"(a[1]), "r"(a[2]), "r"(a[3]), "r"(b[0]), "r"(b[1]));
}

__global__ __launch_bounds__(256, 2)
void gemm_tc_kernel(const int* __restrict__ tgt, int n)
{
    extern __shared__ char smc[];
    const uint32_t smb = s2u(smc);
    const int tid   = threadIdx.x;
    const int wid   = tid >> 5;
    const int lane  = tid & 31;
    const int g     = lane >> 2;
    const int t4    = lane & 3;
    const int warpM = wid >> 2;            // 0..1
    const int warpN = wid & 3;             // 0..3
    const int rowBase = blockIdx.y * 128;
    const int colBase = blockIdx.x * 128;

    // ldmatrix per-lane address components
    const int lm_m   = lane >> 3;                        // matrix index 0..3
    const int lm_r   = (lane & 7) + ((lm_m & 1) << 3);   // row 0..15
    const int lm_cs  = (lm_m >> 1) << 4;                 // 0 or 16 bytes
    const int lm_swz = (lane & 7) << 4;                  // swizzle XOR

    // ---- async chunk loader: A 1024 x 16B + B 1024 x 16B ----
    auto load_chunk = [&](int c, int buf) {
        const uint32_t base = smb + buf * BUFB;
#pragma unroll
        for (int it = 0; it < 8; ++it) {
            int idx = tid + it * 256;       // 0..2047
            int isB = idx >> 10;
            int r   = (idx >> 3) & 127;
            int f   = idx & 7;
            int grow = (isB ? colBase : rowBase) + r;
            uint32_t dst = base + isB * TILEB + r * 128 + ((f * 16) ^ ((r & 7) << 4));
            const __half* src = &g_xh[(size_t)grow * DVAL + c * BK + f * 8];
            asm volatile("cp.async.cg.shared.global [%0], [%1], 16;"
                         :: "r"(dst), "l"(src) : "memory");
        }
        asm volatile("cp.async.commit_group;" ::: "memory");
    };

    float acc[4][4][4];
#pragma unroll
    for (int i = 0; i < 4; i++)
#pragma unroll
        for (int j = 0; j < 4; j++)
#pragma unroll
            for (int q = 0; q < 4; q++) acc[i][j][q] = 0.f;

    load_chunk(0, 0);

    for (int c = 0; c < NCHUNK; ++c) {
        const int buf = c & 1;
        if (c + 1 < NCHUNK) {
            load_chunk(c + 1, buf ^ 1);
            asm volatile("cp.async.wait_group 1;" ::: "memory");
        } else {
            asm volatile("cp.async.wait_group 0;" ::: "memory");
        }
        __syncthreads();

        const uint32_t Abase = smb + buf * BUFB;
        const uint32_t Bbase = Abase + TILEB;

#pragma unroll
        for (int q = 0; q < 4; ++q) {       // 4 k-steps of 16
            const int kb = q * 32;          // bytes
            const uint32_t cswz = (uint32_t)((kb + lm_cs) ^ lm_swz);
            uint32_t af[4][4], bf[4][2];
#pragma unroll
            for (int i = 0; i < 4; ++i) {
                uint32_t addr = Abase + (uint32_t)((warpM * 64 + i * 16 + lm_r) * 128) + cswz;
                asm volatile("ldmatrix.sync.aligned.m8n8.x4.shared.b16 {%0,%1,%2,%3}, [%4];"
                             : "=r"(af[i][0]), "=r"(af[i][1]), "=r"(af[i][2]), "=r"(af[i][3])
                             : "r"(addr));
            }
#pragma unroll
            for (int jj = 0; jj < 2; ++jj) {
                uint32_t r0, r1, r2, r3;
                uint32_t addr = Bbase + (uint32_t)((warpN * 32 + jj * 16 + lm_r) * 128) + cswz;
                asm volatile("ldmatrix.sync.aligned.m8n8.x4.shared.b16 {%0,%1,%2,%3}, [%4];"
                             : "=r"(r0), "=r"(r1), "=r"(r2), "=r"(r3)
                             : "r"(addr));
                bf[jj * 2][0]     = r0; bf[jj * 2][1]     = r2;
                bf[jj * 2 + 1][0] = r1; bf[jj * 2 + 1][1] = r3;
            }
#pragma unroll
            for (int i = 0; i < 4; ++i)
#pragma unroll
                for (int j = 0; j < 4; ++j)
                    mma_f16(acc[i][j], af[i], bf[j]);
        }
        __syncthreads();
    }

    // ---- epilogue: fp16 sim store + fused per-row min-pos / max-neg ----
#pragma unroll
    for (int i = 0; i < 4; ++i) {
        const int r0 = rowBase + warpM * 64 + i * 16 + g;
        const int r1 = r0 + 8;
        const int tr0 = tgt[r0], tr1 = tgt[r1];
        float mp0 = __int_as_float(0x7f800000), mn0 = __int_as_float(0xff800000);
        float mp1 = mp0, mn1 = mn0;
#pragma unroll
        for (int j = 0; j < 4; ++j) {
            const int col = colBase + warpN * 32 + j * 8 + t4 * 2;
            const int tc0 = tgt[col], tc1 = tgt[col + 1];
            float v00 = acc[i][j][0], v01 = acc[i][j][1];
            float v10 = acc[i][j][2], v11 = acc[i][j][3];
            if (tc0 == tr0) { if (col     != r0) mp0 = fminf(mp0, v00); }
            else            mn0 = fmaxf(mn0, v00);
            if (tc1 == tr0) { if (col + 1 != r0) mp0 = fminf(mp0, v01); }
            else            mn0 = fmaxf(mn0, v01);
            if (tc0 == tr1) { if (col     != r1) mp1 = fminf(mp1, v10); }
            else            mn1 = fmaxf(mn1, v10);
            if (tc1 == tr1) { if (col + 1 != r1) mp1 = fminf(mp1, v11); }
            else            mn1 = fmaxf(mn1, v11);

            *(half2*)&g_simh[(size_t)r0 * n + col] = __floats2half2_rn(v00, v01);
            *(half2*)&g_simh[(size_t)r1 * n + col] = __floats2half2_rn(v10, v11);
        }
#pragma unroll
        for (int o = 1; o < 4; o <<= 1) {
            mp0 = fminf(mp0, __shfl_xor_sync(0xffffffffu, mp0, o));
            mn0 = fmaxf(mn0, __shfl_xor_sync(0xffffffffu, mn0, o));
            mp1 = fminf(mp1, __shfl_xor_sync(0xffffffffu, mp1, o));
            mn1 = fmaxf(mn1, __shfl_xor_sync(0xffffffffu, mn1, o));
        }
        if (t4 == 0) {
            atomicMin(&g_minpos_enc[r0], fenc(mp0));
            atomicMax(&g_maxneg_enc[r0], fenc(mn0));
            atomicMin(&g_minpos_enc[r1], fenc(mp1));
            atomicMax(&g_maxneg_enc[r1], fenc(mn1));
        }
    }
}

// ============================================================================
// Pass A': exact fp32 sims of the LAST row. 8-way d-split per column.
// ============================================================================
__global__ __launch_bounds__(256)
void lastrow_kernel(const float* __restrict__ X, int n)
{
    __shared__ float xl[DVAL];
    const int t = threadIdx.x;
    xl[t] = X[(size_t)(n - 1) * DVAL + t];
    __syncthreads();
    const int gt  = blockIdx.x * 256 + t;
    const int col = gt >> 3;
    const int seg = gt & 7;
    const float4* xr  = (const float4*)&X[(size_t)col * DVAL + seg * 32];
    const float4* xl4 = (const float4*)&xl[seg * 32];
    float s = 0.f;
#pragma unroll
    for (int k = 0; k < 8; ++k) {
        float4 a = xr[k], b = xl4[k];
        s += a.x * b.x + a.y * b.y + a.z * b.z + a.w * b.w;
    }
#pragma unroll
    for (int o = 4; o; o >>= 1) s += __shfl_xor_sync(0xffffffffu, s, o);
    if (seg == 0) g_lastsim[col] = s;
}

// ============================================================================
// Pass B: warp-per-row (8 rows per CTA). Targets staged once per CTA.
// ============================================================================
__global__ __launch_bounds__(256)
void row_pass_kernel(const int* __restrict__ tgt,
                     const float* __restrict__ marginp, int n)
{
    extern __shared__ int sh_t[];          // n ints (32 KB)
    const int tid  = threadIdx.x;
    const int w    = tid >> 5;
    const int lane = tid & 31;
    for (int i = tid; i < n; i += 256) sh_t[i] = tgt[i];
    __syncthreads();

    const int row = blockIdx.x * 8 + w;
    const float margin = *marginp;
    const int tr = sh_t[row];
    const float minpos = fdec(g_minpos_enc[row]);
    const float maxneg = fdec(g_maxneg_enc[row]);
    const bool isLast = (row == n - 1);

    float psum = 0.f, nsum = 0.f, pcnt = 0.f, ncnt = 0.f;
    float lps = 0.f, lns = 0.f, lpc = 0.f, lnc = 0.f;

    if (!isLast) {
        const float4* srow4 = (const float4*)(g_simh + (size_t)row * n);
        for (int i = lane; i < n / 8; i += 32) {
            float4 raw = srow4[i];
            const __half2* h2 = (const __half2*)&raw;
            float sv[8];
#pragma unroll
            for (int p = 0; p < 4; ++p) {
                float2 f2 = __half22float2(h2[p]);
                sv[p * 2] = f2.x; sv[p * 2 + 1] = f2.y;
            }
#pragma unroll
            for (int j = 0; j < 8; ++j) {
                int col = i * 8 + j;
                float s = sv[j];
                if (sh_t[col] != tr) {
                    if (s + margin - minpos > 0.f) {
                        nsum += softplus_f(ALPHA * (s - BASE));
                        ncnt += 1.f;
                    }
                } else if (col != row) {
                    if (maxneg - s + margin > 0.f) {
                        psum += softplus_f(-BETA * (s - BASE));
                        pcnt += 1.f;
                    }
                }
            }
        }
    } else {
        const float4* srow4 = (const float4*)g_lastsim;
        for (int i = lane; i < n / 4; i += 32) {
            float4 v = srow4[i];
            float sv[4] = {v.x, v.y, v.z, v.w};
#pragma unroll
            for (int j = 0; j < 4; ++j) {
                int col = i * 4 + j;
                float s = sv[j];
                if (sh_t[col] != tr) {
                    lns += s; lnc += 1.f;
                    if (s + margin - minpos > 0.f) {
                        nsum += softplus_f(ALPHA * (s - BASE));
                        ncnt += 1.f;
                    }
                } else if (col != row) {
                    lps += s; lpc += 1.f;
                    if (maxneg - s + margin > 0.f) {
                        psum += softplus_f(-BETA * (s - BASE));
                        pcnt += 1.f;
                    }
                }
            }
        }
    }

#pragma unroll
    for (int o = 16; o; o >>= 1) {
        psum += __shfl_xor_sync(0xffffffffu, psum, o);
        pcnt += __shfl_xor_sync(0xffffffffu, pcnt, o);
        nsum += __shfl_xor_sync(0xffffffffu, nsum, o);
        ncnt += __shfl_xor_sync(0xffffffffu, ncnt, o);
    }
    if (lane == 0) {
        float pm = psum / fmaxf(pcnt, 1.f);
        float nm = nsum / fmaxf(ncnt, 1.f);
        g_rowloss[row] = (2.f / BETA) * pm + (2.f / ALPHA) * nm;
        g_validf[row]  = (pcnt >= 1.f && ncnt >= 1.f) ? 1 : 0;
    }
    if (isLast) {
#pragma unroll
        for (int o = 16; o; o >>= 1) {
            lps += __shfl_xor_sync(0xffffffffu, lps, o);
            lpc += __shfl_xor_sync(0xffffffffu, lpc, o);
            lns += __shfl_xor_sync(0xffffffffu, lns, o);
            lnc += __shfl_xor_sync(0xffffffffu, lnc, o);
        }
        if (lane == 0) {
            g_last[0] = lps; g_last[1] = lpc;
            g_last[2] = lns; g_last[3] = lnc;
        }
    }
}

// ============================================================================
// Pass C: final deterministic reduction -> out[4]
// ============================================================================
__global__ __launch_bounds__(1024)
void final_kernel(float* __restrict__ out, int n)
{
    const int t = threadIdx.x;
    float ls = 0.f, inv = 0.f;
    for (int i = t; i < n; i += 1024) {
        if (g_validf[i]) ls += g_rowloss[i];
        else             inv += 1.f;
    }
    __shared__ float red[1024];
    __shared__ float red2[1024];
    red[t] = ls; red2[t] = inv; __syncthreads();
    for (int s = 512; s; s >>= 1) {
        if (t < s) { red[t] += red[t + s]; red2[t] += red2[t + s]; }
        __syncthreads();
    }
    if (t == 0) {
        out[0] = red[0] / (float)n;
        out[1] = red2[0] / (float)n;
        out[2] = g_last[0] / fmaxf(g_last[1], 1.f);
        out[3] = g_last[2] / fmaxf(g_last[3], 1.f);
    }
}

// ============================================================================
extern "C" void kernel_launch(void* const* d_in, const int* in_sizes, int n_in,
                              void* d_out, int out_size)
{
    const float* x      = (const float*)d_in[0];
    const int*   tgt    = (const int*)d_in[1];
    const float* margin = (const float*)d_in[2];
    int n = in_sizes[1];

    cudaFuncSetAttribute(gemm_tc_kernel,
                         cudaFuncAttributeMaxDynamicSharedMemorySize, SMEM_BYTES);

    cvt_kernel<<<(n * DVAL / 4 + 255) / 256, 256>>>(x, n * DVAL / 4);
    init_kernel<<<(n + 255) / 256, 256>>>(n);
    dim3 grid(n / 128, n / 128);
    gemm_tc_kernel<<<grid, 256, SMEM_BYTES>>>(tgt, n);
    lastrow_kernel<<<n * 8 / 256, 256>>>(x, n);
    row_pass_kernel<<<n / 8, 256, NMAX * 4>>>(tgt, margin, n);
    final_kernel<<<1, 1024>>>((float*)d_out, n);
}